// round 2
// baseline (speedup 1.0000x reference)
#include <cuda_runtime.h>
#include <cuda_bf16.h>
#include <math.h>

// Problem constants
#define BSZ     64
#define LFULL   88200
#define LP      8820          // pooled length (block_size = 10)
#define NBD     128           // BSZ * 2 directions
#define NC      32            // chunks per (b,dir)
#define CH      276           // chunk length (32*276 = 8832 >= 8820)
#define OUTC    256           // 2*OUT_DIM

// Scratch (static device globals; allocation is forbidden)
__device__ float  g_h[BSZ * LP];               // pooled input        (2.26 MB)
__device__ float4 g_featA[NBD * LP];           // {u0,u1,dt0,dt1}     (18 MB)
__device__ float4 g_featB[NBD * LP];           // {g0,g1,e0,-}        (18 MB)
__device__ float2 g_PQ[NBD * NC * 32];         // per-chunk affine    (1 MB)
__device__ float  g_hin[NBD * NC * 32];        // chunk init states   (0.5 MB)
__device__ float  g_hf[BSZ * LP];              // forward result      (2.26 MB)
__device__ float  g_hb[BSZ * LP];              // backward result     (2.26 MB)

__device__ __forceinline__ float sigm(float x) { return 1.0f / (1.0f + __expf(-x)); }
__device__ __forceinline__ float softplusf(float x) {
    return (x > 20.0f) ? x : log1pf(__expf(x));
}

// ---------------------------------------------------------------------------
// 1) Max-pool x (64, 88200) -> h (64, 8820) over blocks of 10
// ---------------------------------------------------------------------------
__global__ __launch_bounds__(256) void pool_kernel(const float* __restrict__ x) {
    int idx = blockIdx.x * blockDim.x + threadIdx.x;
    if (idx >= BSZ * LP) return;
    const float* p = x + (long long)idx * 10;   // b*88200 + t*10 == idx*10
    float m = p[0];
#pragma unroll
    for (int i = 1; i < 10; i++) m = fmaxf(m, p[i]);
    g_h[idx] = m;
}

// ---------------------------------------------------------------------------
// 2) Per-timestep features (time-parallel): conv+silu -> u, softplus dt,
//    gates g_d = silu(z_d)*ow_d, e0 = ht + sum_d u_d*D_d*g_d (residual folded in)
//    Sequence index s is in scan order (dir=1 already flipped).
// ---------------------------------------------------------------------------
__global__ __launch_bounds__(256) void feat_kernel(
    const float* __restrict__ iw_,   // in_proj_w  (2,1,4)
    const float* __restrict__ cw_,   // conv_w     (2,2,4)
    const float* __restrict__ cb_,   // conv_b     (2,2)
    const float* __restrict__ xpw_,  // x_proj_w   (2,2,33)
    const float* __restrict__ dtw_,  // dt_proj_w  (2,1,2)
    const float* __restrict__ dtb_,  // dt_proj_b  (2,2)
    const float* __restrict__ D_,    // D_ssm      (2,2)
    const float* __restrict__ ow_)   // out_proj_w (2,2,1)
{
    int idx = blockIdx.x * blockDim.x + threadIdx.x;
    if (idx >= NBD * LP) return;
    int s   = idx % LP;
    int bd  = idx / LP;
    int b   = bd & (BSZ - 1);
    int dir = bd >> 6;

    const float* iw = iw_ + dir * 4;

    // ht(s-3..s) in scan order, zero-padded at the left edge
    float ht[4];
#pragma unroll
    for (int k = 0; k < 4; k++) {
        int ss = s - 3 + k;
        float v = 0.0f;
        if (ss >= 0) {
            int t = dir ? (LP - 1 - ss) : ss;
            v = g_h[b * LP + t];
        }
        ht[k] = v;
    }

    // depthwise causal conv (folded with in_proj scalar), then silu
    float conv0 = cb_[dir * 2 + 0];
    float conv1 = cb_[dir * 2 + 1];
#pragma unroll
    for (int k = 0; k < 4; k++) {
        conv0 = fmaf(cw_[dir * 8 + 0 + k] * iw[0], ht[k], conv0);
        conv1 = fmaf(cw_[dir * 8 + 4 + k] * iw[1], ht[k], conv1);
    }
    float u0 = conv0 * sigm(conv0);
    float u1 = conv1 * sigm(conv1);

    const float* xp = xpw_ + dir * 66;
    float dtr = u0 * xp[0] + u1 * xp[33];
    float dt0 = softplusf(fmaf(dtr, dtw_[dir * 2 + 0], dtb_[dir * 2 + 0]));
    float dt1 = softplusf(fmaf(dtr, dtw_[dir * 2 + 1], dtb_[dir * 2 + 1]));

    float htc = ht[3];
    float z0 = htc * iw[2];
    float z1 = htc * iw[3];
    float g0 = z0 * sigm(z0) * ow_[dir * 2 + 0];
    float g1 = z1 * sigm(z1) * ow_[dir * 2 + 1];
    float e0 = htc + u0 * D_[dir * 2 + 0] * g0 + u1 * D_[dir * 2 + 1] * g1;

    g_featA[idx] = make_float4(u0, u1, dt0, dt1);
    g_featB[idx] = make_float4(g0, g1, e0, 0.0f);
}

// ---------------------------------------------------------------------------
// 3) Phase A: per-chunk local scan from zero state -> affine map (P, Q).
//    One warp per (b,dir,chunk); lane = (d<<4)|n handles one state channel.
// ---------------------------------------------------------------------------
__global__ __launch_bounds__(256) void scanA_kernel(
    const float* __restrict__ xpw_, const float* __restrict__ Alog_)
{
    int gtid = blockIdx.x * blockDim.x + threadIdx.x;
    int wid  = gtid >> 5;
    if (wid >= NBD * NC) return;
    int lane  = threadIdx.x & 31;
    int bd    = wid >> 5;          // NC = 32
    int chunk = wid & (NC - 1);
    int d     = lane >> 4;
    int n     = lane & 15;
    int dir   = bd >> 6;

    float A = -expf(Alog_[dir * 32 + d * 16 + n]);
    const float* xp = xpw_ + dir * 66;
    float xB0 = xp[1 + n], xB1 = xp[33 + 1 + n];

    int s0 = chunk * CH;
    int s1 = min(s0 + CH, LP);
    const float4* fA = g_featA + bd * LP;

    float P = 1.0f, hst = 0.0f;
    bool hi = (d != 0);
#pragma unroll 4
    for (int s = s0; s < s1; s++) {
        float4 f  = fA[s];
        float ud  = hi ? f.y : f.x;
        float dtd = hi ? f.w : f.z;
        float Bc  = fmaf(f.x, xB0, f.y * xB1);
        float dA  = __expf(dtd * A);
        hst = fmaf(dA, hst, dtd * Bc * ud);
        P  *= dA;
    }
    g_PQ[wid * 32 + lane] = make_float2(P, hst);
}

// ---------------------------------------------------------------------------
// 4) Phase B: sequential prefix across the 32 chunks (tiny).
// ---------------------------------------------------------------------------
__global__ __launch_bounds__(256) void scanB_kernel() {
    int tid = blockIdx.x * blockDim.x + threadIdx.x;
    if (tid >= NBD * 32) return;
    int bd = tid >> 5, lane = tid & 31;
    float cur = 0.0f;
#pragma unroll
    for (int k = 0; k < NC; k++) {
        int i = (bd * NC + k) * 32 + lane;
        g_hin[i] = cur;
        float2 pq = g_PQ[i];
        cur = fmaf(pq.x, cur, pq.y);
    }
}

// ---------------------------------------------------------------------------
// 5) Phase C: replay scan with correct init state, emit hf / hb.
// ---------------------------------------------------------------------------
__global__ __launch_bounds__(256) void scanC_kernel(
    const float* __restrict__ xpw_, const float* __restrict__ Alog_)
{
    int gtid = blockIdx.x * blockDim.x + threadIdx.x;
    int wid  = gtid >> 5;
    if (wid >= NBD * NC) return;
    int lane  = threadIdx.x & 31;
    int bd    = wid >> 5;
    int chunk = wid & (NC - 1);
    int d     = lane >> 4;
    int n     = lane & 15;
    int dir   = bd >> 6;
    int b     = bd & (BSZ - 1);

    float A = -expf(Alog_[dir * 32 + d * 16 + n]);
    const float* xp = xpw_ + dir * 66;
    float xB0 = xp[1 + n],  xB1 = xp[33 + 1 + n];
    float xC0 = xp[17 + n], xC1 = xp[33 + 17 + n];

    int s0 = chunk * CH;
    int s1 = min(s0 + CH, LP);
    const float4* fA = g_featA + bd * LP;
    const float4* fB = g_featB + bd * LP;

    float hst = g_hin[wid * 32 + lane];
    bool hi = (d != 0);
#pragma unroll 2
    for (int s = s0; s < s1; s++) {
        float4 f  = fA[s];
        float4 fb = fB[s];
        float ud  = hi ? f.y : f.x;
        float dtd = hi ? f.w : f.z;
        float Bc  = fmaf(f.x, xB0, f.y * xB1);
        float dA  = __expf(dtd * A);
        hst = fmaf(dA, hst, dtd * Bc * ud);

        float v = hst * fmaf(f.x, xC0, f.y * xC1);
        v += __shfl_xor_sync(0xffffffffu, v, 8);
        v += __shfl_xor_sync(0xffffffffu, v, 4);
        v += __shfl_xor_sync(0xffffffffu, v, 2);
        v += __shfl_xor_sync(0xffffffffu, v, 1);     // y_d on all lanes of half
        float t = v * (hi ? fb.y : fb.x);
        t += __shfl_xor_sync(0xffffffffu, t, 16);    // sum over d
        if (lane == 0) {
            float res = t + fb.z;                    // + residual + u*D*g terms
            if (dir == 0) g_hf[b * LP + s] = res;
            else          g_hb[b * LP + (LP - 1 - s)] = res;
        }
    }
}

// ---------------------------------------------------------------------------
// 6) Final MLP + transpose + split: out[b,c,t] = hf*w0c + hb*w1c + bc
//    gamma = channels [0,128), beta = channels [128,256) (separate halves of out)
//    Tiled through smem so hf/hb are read once per tile, writes fully coalesced.
// ---------------------------------------------------------------------------
#define TVT 32   // float4 t-vectors per tile (128 timesteps)

__global__ __launch_bounds__(256) void mlp_kernel(
    const float* __restrict__ mlp_w, const float* __restrict__ mlp_b,
    float* __restrict__ out)
{
    __shared__ float4 shf[TVT];
    __shared__ float4 shb[TVT];
    int b    = blockIdx.y;
    int tile = blockIdx.x;
    int tid  = threadIdx.x;
    const int NV = LP / 4;                 // 2205 float4 per row

    if (tid < TVT) {
        int tv = tile * TVT + tid;
        shf[tid] = (tv < NV) ? ((const float4*)g_hf)[b * NV + tv]
                             : make_float4(0, 0, 0, 0);
    } else if (tid < 2 * TVT) {
        int tv = tile * TVT + (tid - TVT);
        shb[tid - TVT] = (tv < NV) ? ((const float4*)g_hb)[b * NV + tv]
                                   : make_float4(0, 0, 0, 0);
    }
    __syncthreads();

    int tvi = tid & 31;
    int cg  = tid >> 5;                    // 8 channels per iteration
    int tv  = tile * TVT + tvi;
    if (tv >= NV) return;
    float4 a = shf[tvi];
    float4 v = shb[tvi];

    const long long G = (long long)BSZ * 128 * LP;   // gamma/beta split offset
#pragma unroll 4
    for (int g = 0; g < 32; g++) {
        int c = g * 8 + cg;
        float w0 = mlp_w[c];
        float w1 = mlp_w[OUTC + c];
        float bc = mlp_b[c];
        float4 o;
        o.x = fmaf(a.x, w0, fmaf(v.x, w1, bc));
        o.y = fmaf(a.y, w0, fmaf(v.y, w1, bc));
        o.z = fmaf(a.z, w0, fmaf(v.z, w1, bc));
        o.w = fmaf(a.w, w0, fmaf(v.w, w1, bc));
        long long off;
        if (c < 128) off = (long long)b * 128 * LP + (long long)c * LP + tv * 4;
        else         off = G + (long long)b * 128 * LP + (long long)(c - 128) * LP + tv * 4;
        *(float4*)(out + off) = o;
    }
}

// ---------------------------------------------------------------------------
extern "C" void kernel_launch(void* const* d_in, const int* in_sizes, int n_in,
                              void* d_out, int out_size)
{
    const float* x    = (const float*)d_in[0];
    const float* ipw  = (const float*)d_in[1];
    const float* cw   = (const float*)d_in[2];
    const float* cb   = (const float*)d_in[3];
    const float* xpw  = (const float*)d_in[4];
    const float* dtw  = (const float*)d_in[5];
    const float* dtb  = (const float*)d_in[6];
    const float* Alog = (const float*)d_in[7];
    const float* Dssm = (const float*)d_in[8];
    const float* opw  = (const float*)d_in[9];
    const float* mw   = (const float*)d_in[10];
    const float* mb   = (const float*)d_in[11];
    float* out = (float*)d_out;

    pool_kernel<<<(BSZ * LP + 255) / 256, 256>>>(x);
    feat_kernel<<<(NBD * LP + 255) / 256, 256>>>(ipw, cw, cb, xpw, dtw, dtb, Dssm, opw);
    scanA_kernel<<<(NBD * NC * 32 + 255) / 256, 256>>>(xpw, Alog);
    scanB_kernel<<<(NBD * 32 + 255) / 256, 256>>>();
    scanC_kernel<<<(NBD * NC * 32 + 255) / 256, 256>>>(xpw, Alog);
    {
        dim3 grid((LP / 4 + TVT - 1) / TVT, BSZ);
        mlp_kernel<<<grid, 256>>>(mw, mb, out);
    }
}